// round 1
// baseline (speedup 1.0000x reference)
#include <cuda_runtime.h>
#include <math.h>

#define BC 48          // 16 batch * 3 channels
#define WS 11
#define TW 32
#define TH 32

// ---------------- device globals (scratch; no runtime allocation) -----------
__device__ float  g_win[WS];
__device__ double g_cs[5];
__device__ double g_ss[5];
// ping-pong pooled pyramids
__device__ float g_xa[BC * 256 * 256];
__device__ float g_ya[BC * 256 * 256];
__device__ float g_xb[BC * 128 * 128];
__device__ float g_yb[BC * 128 * 128];

// ---------------- init: gaussian window + zero accumulators -----------------
__global__ void init_kernel() {
    if (threadIdx.x == 0) {
        float g[WS];
        float s = 0.f;
        #pragma unroll
        for (int i = 0; i < WS; i++) {
            float d = (float)(i - WS / 2);
            g[i] = expf(-(d * d) / (2.0f * 1.5f * 1.5f));
            s += g[i];
        }
        #pragma unroll
        for (int i = 0; i < WS; i++) g_win[i] = g[i] / s;
        #pragma unroll
        for (int i = 0; i < 5; i++) { g_cs[i] = 0.0; g_ss[i] = 0.0; }
    }
}

// ---------------- fused separable conv + SSIM stats + reduction -------------
// One block = 32x32 output tile of one (b,c) image. Computes the five
// gaussian-filtered moments via separable h-pass/v-pass in smem, evaluates
// cs/ssim per pixel, reduces, atomically accumulates per-level double sums.
__global__ __launch_bounds__(256) void ssim_level_kernel(
    const float* __restrict__ X, const float* __restrict__ Y,
    int H, int W, int level)
{
    __shared__ float sx[TH + 10][TW + 12];   // +2 pad vs 42 to dodge conflicts
    __shared__ float sy[TH + 10][TW + 12];
    __shared__ float hx [TH + 10][TW];
    __shared__ float hy [TH + 10][TW];
    __shared__ float hxx[TH + 10][TW];
    __shared__ float hyy[TH + 10][TW];
    __shared__ float hxy[TH + 10][TW];
    __shared__ float wsm[WS];
    __shared__ double red0[8], red1[8];

    const int tid = threadIdx.x;             // 256 threads
    if (tid < WS) wsm[tid] = g_win[tid];

    const int img  = blockIdx.z;
    const float* Xi = X + (size_t)img * H * W;
    const float* Yi = Y + (size_t)img * H * W;
    const int row0 = blockIdx.y * TH;
    const int col0 = blockIdx.x * TW;
    __syncthreads();

    // ---- load (TH+10)x(TW+10) input tiles (zero-pad OOB; OOB never used) ----
    for (int i = tid; i < (TH + 10) * (TW + 10); i += 256) {
        int r = i / (TW + 10), c = i % (TW + 10);
        int gr = row0 + r, gc = col0 + c;
        float xv = 0.f, yv = 0.f;
        if (gr < H && gc < W) {
            xv = Xi[(size_t)gr * W + gc];
            yv = Yi[(size_t)gr * W + gc];
        }
        sx[r][c] = xv;
        sy[r][c] = yv;
    }
    __syncthreads();

    // ---- horizontal pass: 5 moments, (TH+10) x TW items ----
    for (int i = tid; i < (TH + 10) * TW; i += 256) {
        int r = i / TW, c = i % TW;
        float gx = 0.f, gy = 0.f, gxx = 0.f, gyy = 0.f, gxy = 0.f;
        #pragma unroll
        for (int k = 0; k < WS; k++) {
            float w = wsm[k];
            float x = sx[r][c + k];
            float y = sy[r][c + k];
            float wx = w * x, wy = w * y;
            gx += wx;
            gy += wy;
            gxx = fmaf(wx, x, gxx);
            gyy = fmaf(wy, y, gyy);
            gxy = fmaf(wx, y, gxy);
        }
        hx [r][c] = gx;  hy [r][c] = gy;
        hxx[r][c] = gxx; hyy[r][c] = gyy; hxy[r][c] = gxy;
    }
    __syncthreads();

    // ---- vertical pass + per-pixel SSIM math + accumulate ----
    const float C1 = 0.01f * 0.01f;
    const float C2 = 0.03f * 0.03f;
    const int c  = tid & 31;
    const int rb = tid >> 5;
    const int Hout = H - 10, Wout = W - 10;
    const bool colok = (col0 + c) < Wout;

    float cs_sum = 0.f, ss_sum = 0.f;
    #pragma unroll
    for (int i = 0; i < 4; i++) {
        int r = rb + i * 8;
        if (colok && (row0 + r) < Hout) {
            float mu1 = 0.f, mu2 = 0.f, e11 = 0.f, e22 = 0.f, e12 = 0.f;
            #pragma unroll
            for (int k = 0; k < WS; k++) {
                float w = wsm[k];
                mu1 = fmaf(w, hx [r + k][c], mu1);
                mu2 = fmaf(w, hy [r + k][c], mu2);
                e11 = fmaf(w, hxx[r + k][c], e11);
                e22 = fmaf(w, hyy[r + k][c], e22);
                e12 = fmaf(w, hxy[r + k][c], e12);
            }
            float s1  = e11 - mu1 * mu1;
            float s2  = e22 - mu2 * mu2;
            float s12 = e12 - mu1 * mu2;
            float num = 2.f * s12 + C2;
            float den = s1 + s2 + C2;
            float cs  = num / den;
            float lum = (2.f * mu1 * mu2 + C1) / (mu1 * mu1 + mu2 * mu2 + C1);
            cs_sum += cs;
            ss_sum += lum * cs;
        }
    }

    // warp + block reduction
    #pragma unroll
    for (int o = 16; o > 0; o >>= 1) {
        cs_sum += __shfl_down_sync(0xffffffffu, cs_sum, o);
        ss_sum += __shfl_down_sync(0xffffffffu, ss_sum, o);
    }
    if ((tid & 31) == 0) { red0[tid >> 5] = cs_sum; red1[tid >> 5] = ss_sum; }
    __syncthreads();
    if (tid == 0) {
        double a = 0.0, b = 0.0;
        #pragma unroll
        for (int w = 0; w < 8; w++) { a += red0[w]; b += red1[w]; }
        atomicAdd(&g_cs[level], a);
        atomicAdd(&g_ss[level], b);
    }
}

// ---------------- 2x2 average pool (stride 2, floor) ------------------------
__global__ void pool2_kernel(const float* __restrict__ in, float* __restrict__ out,
                             int Ho, int Wo)
{
    int idx = blockIdx.x * blockDim.x + threadIdx.x;
    int total = BC * Ho * Wo;
    if (idx >= total) return;
    int w = idx % Wo;
    int t = idx / Wo;
    int h = t % Ho;
    int img = t / Ho;
    int Wi = Wo * 2;
    const float* p = in + (((size_t)img * (Ho * 2) + 2 * h) * Wi + 2 * w);
    out[idx] = 0.25f * (p[0] + p[1] + p[Wi] + p[Wi + 1]);
}

// ---------------- final combine ----------------------------------------------
__global__ void finish_kernel(float* __restrict__ out)
{
    if (threadIdx.x != 0) return;
    const double w[5] = {0.0448, 0.2856, 0.3001, 0.2363, 0.1333};
    double ms = 1.0;
    #pragma unroll
    for (int l = 0; l < 5; l++) {
        int Hl = 512 >> l;
        double n  = 48.0 * (double)(Hl - 10) * (double)(Hl - 10);
        double cs = g_cs[l] / n; if (cs < 0.0) cs = 0.0; cs = (cs + 1.0) * 0.5;
        double ss = g_ss[l] / n; if (ss < 0.0) ss = 0.0; ss = (ss + 1.0) * 0.5;
        double v  = (l < 4) ? cs : ss;
        ms *= pow(v, w[l]);
    }
    out[0] = (float)(1.0 - ms);
}

// ---------------- host launch -------------------------------------------------
static inline dim3 conv_grid(int H, int W) {
    int Hout = H - 10, Wout = W - 10;
    return dim3((Wout + TW - 1) / TW, (Hout + TH - 1) / TH, BC);
}

extern "C" void kernel_launch(void* const* d_in, const int* in_sizes, int n_in,
                              void* d_out, int out_size)
{
    const float* X0 = (const float*)d_in[0];
    const float* Y0 = (const float*)d_in[1];
    float* out = (float*)d_out;

    float *xa, *ya, *xb, *yb;
    cudaGetSymbolAddress((void**)&xa, g_xa);
    cudaGetSymbolAddress((void**)&ya, g_ya);
    cudaGetSymbolAddress((void**)&xb, g_xb);
    cudaGetSymbolAddress((void**)&yb, g_yb);

    init_kernel<<<1, 32>>>();

    // ---- level 0: 512 ----
    ssim_level_kernel<<<conv_grid(512, 512), 256>>>(X0, Y0, 512, 512, 0);
    {
        int Ho = 256, Wo = 256, n = BC * Ho * Wo;
        pool2_kernel<<<(n + 255) / 256, 256>>>(X0, xa, Ho, Wo);
        pool2_kernel<<<(n + 255) / 256, 256>>>(Y0, ya, Ho, Wo);
    }
    // ---- level 1: 256 ----
    ssim_level_kernel<<<conv_grid(256, 256), 256>>>(xa, ya, 256, 256, 1);
    {
        int Ho = 128, Wo = 128, n = BC * Ho * Wo;
        pool2_kernel<<<(n + 255) / 256, 256>>>(xa, xb, Ho, Wo);
        pool2_kernel<<<(n + 255) / 256, 256>>>(ya, yb, Ho, Wo);
    }
    // ---- level 2: 128 ----
    ssim_level_kernel<<<conv_grid(128, 128), 256>>>(xb, yb, 128, 128, 2);
    {
        int Ho = 64, Wo = 64, n = BC * Ho * Wo;
        pool2_kernel<<<(n + 255) / 256, 256>>>(xb, xa, Ho, Wo);
        pool2_kernel<<<(n + 255) / 256, 256>>>(yb, ya, Ho, Wo);
    }
    // ---- level 3: 64 ----
    ssim_level_kernel<<<conv_grid(64, 64), 256>>>(xa, ya, 64, 64, 3);
    {
        int Ho = 32, Wo = 32, n = BC * Ho * Wo;
        pool2_kernel<<<(n + 255) / 256, 256>>>(xa, xb, Ho, Wo);
        pool2_kernel<<<(n + 255) / 256, 256>>>(ya, yb, Ho, Wo);
    }
    // ---- level 4: 32 ----
    ssim_level_kernel<<<conv_grid(32, 32), 256>>>(xb, yb, 32, 32, 4);

    finish_kernel<<<1, 32>>>(out);
}

// round 2
// speedup vs baseline: 1.1918x; 1.1918x over previous
#include <cuda_runtime.h>
#include <math.h>

#define BC 48          // 16 batch * 3 channels
#define WS 11
#define TW 32
#define TH 32
#define PITCH_IN 45    // smem pitch for input tiles (conflict-free for 4-row strided reads)
#define PITCH_H  33    // smem pitch for h-pass arrays

// ---------------- device globals (scratch; no runtime allocation) -----------
__device__ float  g_win[WS];
__device__ double g_cs[5];
__device__ double g_ss[5];
// ping-pong pooled pyramids
__device__ float g_xa[BC * 256 * 256];
__device__ float g_ya[BC * 256 * 256];
__device__ float g_xb[BC * 128 * 128];
__device__ float g_yb[BC * 128 * 128];

// ---------------- init: gaussian window + zero accumulators -----------------
__global__ void init_kernel() {
    if (threadIdx.x == 0) {
        float g[WS];
        float s = 0.f;
        #pragma unroll
        for (int i = 0; i < WS; i++) {
            float d = (float)(i - WS / 2);
            g[i] = expf(-(d * d) / (2.0f * 1.5f * 1.5f));
            s += g[i];
        }
        #pragma unroll
        for (int i = 0; i < WS; i++) g_win[i] = g[i] / s;
        #pragma unroll
        for (int i = 0; i < 5; i++) { g_cs[i] = 0.0; g_ss[i] = 0.0; }
    }
}

// ---------------- fused: separable conv + SSIM stats + 2x2 pool -------------
// One block = 32x32 output tile of one (b,c) image.
//  - loads (TH+10)x(TW+10) input tiles into smem
//  - pools its own 32x32 input sub-tile to the next pyramid level (from smem)
//  - h-pass: 4-column register sliding window -> 5 moment arrays in smem
//  - v-pass: 4-row register blocking, per-pixel SSIM math, block reduction
__global__ __launch_bounds__(256) void ssim_level_kernel(
    const float* __restrict__ X, const float* __restrict__ Y,
    float* __restrict__ XP, float* __restrict__ YP,
    int H, int W, int level, int do_pool)
{
    __shared__ float sx[(TH + 10) * PITCH_IN];
    __shared__ float sy[(TH + 10) * PITCH_IN];
    __shared__ float hx [(TH + 10) * PITCH_H];
    __shared__ float hy [(TH + 10) * PITCH_H];
    __shared__ float hxx[(TH + 10) * PITCH_H];
    __shared__ float hyy[(TH + 10) * PITCH_H];
    __shared__ float hxy[(TH + 10) * PITCH_H];
    __shared__ float wsm[WS];
    __shared__ double red0[8], red1[8];

    const int tid = threadIdx.x;             // 256 threads
    if (tid < WS) wsm[tid] = g_win[tid];

    const int img  = blockIdx.z;
    const float* Xi = X + (size_t)img * H * W;
    const float* Yi = Y + (size_t)img * H * W;
    const int row0 = blockIdx.y * TH;
    const int col0 = blockIdx.x * TW;
    __syncthreads();

    // weights to registers
    float wreg[WS];
    #pragma unroll
    for (int k = 0; k < WS; k++) wreg[k] = wsm[k];

    // ---- load (TH+10)x(TW+10) input tiles (zero-pad OOB; OOB never used) ----
    for (int i = tid; i < (TH + 10) * (TW + 10); i += 256) {
        int r = i / (TW + 10), c = i % (TW + 10);
        int gr = row0 + r, gc = col0 + c;
        float xv = 0.f, yv = 0.f;
        if (gr < H && gc < W) {
            xv = Xi[(size_t)gr * W + gc];
            yv = Yi[(size_t)gr * W + gc];
        }
        sx[r * PITCH_IN + c] = xv;
        sy[r * PITCH_IN + c] = yv;
    }
    __syncthreads();

    // ---- fused 2x2 avg pool of this block's 32x32 input sub-tile ----
    if (do_pool) {
        int pr = tid >> 4, pc = tid & 15;        // 16x16 pooled outputs
        const float* px = &sx[(2 * pr) * PITCH_IN + 2 * pc];
        const float* py = &sy[(2 * pr) * PITCH_IN + 2 * pc];
        float xp = 0.25f * (px[0] + px[1] + px[PITCH_IN] + px[PITCH_IN + 1]);
        float yp = 0.25f * (py[0] + py[1] + py[PITCH_IN] + py[PITCH_IN + 1]);
        int Ho = H >> 1, Wo = W >> 1;
        size_t o = (size_t)img * Ho * Wo + (size_t)((row0 >> 1) + pr) * Wo + (col0 >> 1) + pc;
        XP[o] = xp;
        YP[o] = yp;
    }

    // ---- horizontal pass: 4-column sliding window, 5 moments ----
    // 42 rows x 8 column-groups = 336 work units
    for (int u = tid; u < (TH + 10) * 8; u += 256) {
        int r = u >> 3, cg = (u & 7) << 2;
        float xv[14], yv[14];
        #pragma unroll
        for (int i = 0; i < 14; i++) {
            xv[i] = sx[r * PITCH_IN + cg + i];
            yv[i] = sy[r * PITCH_IN + cg + i];
        }
        float gx[4]  = {0, 0, 0, 0}, gy[4]  = {0, 0, 0, 0};
        float gxx[4] = {0, 0, 0, 0}, gyy[4] = {0, 0, 0, 0}, gxy[4] = {0, 0, 0, 0};
        #pragma unroll
        for (int k = 0; k < WS; k++) {
            float w = wreg[k];
            #pragma unroll
            for (int j = 0; j < 4; j++) {
                float x = xv[k + j], y = yv[k + j];
                float wx = w * x, wy = w * y;
                gx[j] += wx;
                gy[j] += wy;
                gxx[j] = fmaf(wx, x, gxx[j]);
                gyy[j] = fmaf(wy, y, gyy[j]);
                gxy[j] = fmaf(wx, y, gxy[j]);
            }
        }
        #pragma unroll
        for (int j = 0; j < 4; j++) {
            hx [r * PITCH_H + cg + j] = gx[j];
            hy [r * PITCH_H + cg + j] = gy[j];
            hxx[r * PITCH_H + cg + j] = gxx[j];
            hyy[r * PITCH_H + cg + j] = gyy[j];
            hxy[r * PITCH_H + cg + j] = gxy[j];
        }
    }
    __syncthreads();

    // ---- vertical pass: 4-row register blocking + SSIM math ----
    const float C1 = 0.01f * 0.01f;
    const float C2 = 0.03f * 0.03f;
    const int c  = tid & 31;
    const int r0 = (tid >> 5) << 2;           // 0,4,...,28
    const int Hout = H - 10, Wout = W - 10;
    const bool colok = (col0 + c) < Wout;

    float a_mu1[4] = {0, 0, 0, 0}, a_mu2[4] = {0, 0, 0, 0};
    float a_e11[4] = {0, 0, 0, 0}, a_e22[4] = {0, 0, 0, 0}, a_e12[4] = {0, 0, 0, 0};
    #pragma unroll
    for (int k = 0; k < 14; k++) {
        float v0 = hx [(r0 + k) * PITCH_H + c];
        float v1 = hy [(r0 + k) * PITCH_H + c];
        float v2 = hxx[(r0 + k) * PITCH_H + c];
        float v3 = hyy[(r0 + k) * PITCH_H + c];
        float v4 = hxy[(r0 + k) * PITCH_H + c];
        #pragma unroll
        for (int j = 0; j < 4; j++) {
            int t = k - j;
            if (t >= 0 && t < WS) {
                float w = wreg[t];
                a_mu1[j] = fmaf(w, v0, a_mu1[j]);
                a_mu2[j] = fmaf(w, v1, a_mu2[j]);
                a_e11[j] = fmaf(w, v2, a_e11[j]);
                a_e22[j] = fmaf(w, v3, a_e22[j]);
                a_e12[j] = fmaf(w, v4, a_e12[j]);
            }
        }
    }

    float cs_sum = 0.f, ss_sum = 0.f;
    #pragma unroll
    for (int j = 0; j < 4; j++) {
        if (colok && (row0 + r0 + j) < Hout) {
            float mu1 = a_mu1[j], mu2 = a_mu2[j];
            float s1  = a_e11[j] - mu1 * mu1;
            float s2  = a_e22[j] - mu2 * mu2;
            float s12 = a_e12[j] - mu1 * mu2;
            float num = 2.f * s12 + C2;
            float den = s1 + s2 + C2;
            float cs  = num / den;
            float lum = (2.f * mu1 * mu2 + C1) / (mu1 * mu1 + mu2 * mu2 + C1);
            cs_sum += cs;
            ss_sum += lum * cs;
        }
    }

    // warp + block reduction
    #pragma unroll
    for (int o = 16; o > 0; o >>= 1) {
        cs_sum += __shfl_down_sync(0xffffffffu, cs_sum, o);
        ss_sum += __shfl_down_sync(0xffffffffu, ss_sum, o);
    }
    if ((tid & 31) == 0) { red0[tid >> 5] = cs_sum; red1[tid >> 5] = ss_sum; }
    __syncthreads();
    if (tid == 0) {
        double a = 0.0, b = 0.0;
        #pragma unroll
        for (int w = 0; w < 8; w++) { a += red0[w]; b += red1[w]; }
        atomicAdd(&g_cs[level], a);
        atomicAdd(&g_ss[level], b);
    }
}

// ---------------- final combine ----------------------------------------------
__global__ void finish_kernel(float* __restrict__ out)
{
    if (threadIdx.x != 0) return;
    const double w[5] = {0.0448, 0.2856, 0.3001, 0.2363, 0.1333};
    double ms = 1.0;
    #pragma unroll
    for (int l = 0; l < 5; l++) {
        int Hl = 512 >> l;
        double n  = 48.0 * (double)(Hl - 10) * (double)(Hl - 10);
        double cs = g_cs[l] / n; if (cs < 0.0) cs = 0.0; cs = (cs + 1.0) * 0.5;
        double ss = g_ss[l] / n; if (ss < 0.0) ss = 0.0; ss = (ss + 1.0) * 0.5;
        double v  = (l < 4) ? cs : ss;
        ms *= pow(v, w[l]);
    }
    out[0] = (float)(1.0 - ms);
}

// ---------------- host launch -------------------------------------------------
static inline dim3 conv_grid(int H, int W) {
    int Hout = H - 10, Wout = W - 10;
    return dim3((Wout + TW - 1) / TW, (Hout + TH - 1) / TH, BC);
}

extern "C" void kernel_launch(void* const* d_in, const int* in_sizes, int n_in,
                              void* d_out, int out_size)
{
    const float* X0 = (const float*)d_in[0];
    const float* Y0 = (const float*)d_in[1];
    float* out = (float*)d_out;

    float *xa, *ya, *xb, *yb;
    cudaGetSymbolAddress((void**)&xa, g_xa);
    cudaGetSymbolAddress((void**)&ya, g_ya);
    cudaGetSymbolAddress((void**)&xb, g_xb);
    cudaGetSymbolAddress((void**)&yb, g_yb);

    init_kernel<<<1, 32>>>();

    // level 0: 512 -> pool into xa/ya (256)
    ssim_level_kernel<<<conv_grid(512, 512), 256>>>(X0, Y0, xa, ya, 512, 512, 0, 1);
    // level 1: 256 -> pool into xb/yb (128)
    ssim_level_kernel<<<conv_grid(256, 256), 256>>>(xa, ya, xb, yb, 256, 256, 1, 1);
    // level 2: 128 -> pool into xa/ya (64)
    ssim_level_kernel<<<conv_grid(128, 128), 256>>>(xb, yb, xa, ya, 128, 128, 2, 1);
    // level 3: 64 -> pool into xb/yb (32)
    ssim_level_kernel<<<conv_grid(64, 64), 256>>>(xa, ya, xb, yb, 64, 64, 3, 1);
    // level 4: 32, no pool
    ssim_level_kernel<<<conv_grid(32, 32), 256>>>(xb, yb, nullptr, nullptr, 32, 32, 4, 0);

    finish_kernel<<<1, 32>>>(out);
}

// round 3
// speedup vs baseline: 1.4881x; 1.2486x over previous
#include <cuda_runtime.h>
#include <math.h>

#define BC 48          // 16 batch * 3 channels
#define WS 11

typedef unsigned long long u64;

// ---------------- f32x2 packed-math helpers (sm_103a) ------------------------
__device__ __forceinline__ u64 pk2(float lo, float hi) {
    u64 r; asm("mov.b64 %0,{%1,%2};" : "=l"(r) : "f"(lo), "f"(hi)); return r;
}
__device__ __forceinline__ void up2(u64 v, float& a, float& b) {
    asm("mov.b64 {%0,%1},%2;" : "=f"(a), "=f"(b) : "l"(v));
}
__device__ __forceinline__ u64 fma2(u64 a, u64 b, u64 c) {
    u64 d; asm("fma.rn.f32x2 %0,%1,%2,%3;" : "=l"(d) : "l"(a), "l"(b), "l"(c)); return d;
}
__device__ __forceinline__ u64 mul2(u64 a, u64 b) {
    u64 d; asm("mul.rn.f32x2 %0,%1,%2;" : "=l"(d) : "l"(a), "l"(b)); return d;
}

// ---------------- device globals (scratch; no runtime allocation) -----------
__device__ float  g_win[WS];
__device__ double g_cs[5];
__device__ double g_ss[5];
__device__ float g_xa[BC * 256 * 256];
__device__ float g_ya[BC * 256 * 256];
__device__ float g_xb[BC * 128 * 128];
__device__ float g_yb[BC * 128 * 128];

// ---------------- init: gaussian window + zero accumulators -----------------
__global__ void init_kernel() {
    if (threadIdx.x == 0) {
        float g[WS];
        float s = 0.f;
        #pragma unroll
        for (int i = 0; i < WS; i++) {
            float d = (float)(i - WS / 2);
            g[i] = expf(-(d * d) / (2.0f * 1.5f * 1.5f));
            s += g[i];
        }
        #pragma unroll
        for (int i = 0; i < WS; i++) g_win[i] = g[i] / s;
        #pragma unroll
        for (int i = 0; i < 5; i++) { g_cs[i] = 0.0; g_ss[i] = 0.0; }
    }
}

// ---------------- fused: separable conv + SSIM stats + 2x2 pool -------------
// Moments filtered: packed (x,y), packed (x^2,y^2), scalar (x+y)^2.
// sigma12 recovered via E[(x+y)^2] = E[x^2]+E[y^2]+2E[xy].
template<int TW, int TH, int NT>
__global__ __launch_bounds__(NT) void ssim_kernel(
    const float* __restrict__ X, const float* __restrict__ Y,
    float* __restrict__ XP, float* __restrict__ YP,
    int H, int W, int level, int do_pool)
{
    constexpr int TIH = TH + 10, TIW = TW + 10;
    constexpr int PIN = TIW | 1;          // odd pitch (float2 units)
    constexpr int PH  = TW + 1;           // odd pitch for h-arrays
    constexpr int CG  = TW / 4;           // column groups in h-pass
    constexpr int RPT = (TH * TW) / NT;   // output rows per thread in v-pass
    constexpr int NW  = NT / 32;

    __shared__ float2 s_in[TIH * PIN];    // packed (x,y)
    __shared__ float2 h01 [TIH * PH];     // packed (gx,gy)
    __shared__ float2 h23 [TIH * PH];     // packed (gxx,gyy)
    __shared__ float  hzz [TIH * PH];     // g(x+y)^2
    __shared__ float  wsm[WS];
    __shared__ double red0[NW], red1[NW];

    const int tid = threadIdx.x;
    if (tid < WS) wsm[tid] = g_win[tid];

    const int img  = blockIdx.z;
    const float* Xi = X + (size_t)img * H * W;
    const float* Yi = Y + (size_t)img * H * W;
    const int row0 = blockIdx.y * TH;
    const int col0 = blockIdx.x * TW;
    __syncthreads();

    float wreg[WS];
    u64   wpk [WS];
    #pragma unroll
    for (int k = 0; k < WS; k++) { wreg[k] = wsm[k]; wpk[k] = pk2(wreg[k], wreg[k]); }

    // ---- load (TIH)x(TIW) input tile as packed float2 ----
    for (int i = tid; i < TIH * TIW; i += NT) {
        int r = i / TIW, c = i % TIW;
        int gr = row0 + r, gc = col0 + c;
        float xv = 0.f, yv = 0.f;
        if (gr < H && gc < W) {
            xv = Xi[(size_t)gr * W + gc];
            yv = Yi[(size_t)gr * W + gc];
        }
        s_in[r * PIN + c] = make_float2(xv, yv);
    }
    __syncthreads();

    // ---- fused 2x2 avg pool of this block's THxTW input sub-tile ----
    if (do_pool) {
        constexpr int PW = TW / 2, PHh = TH / 2;
        if (tid < PW * PHh) {
            int pr = tid / PW, pc = tid % PW;
            float2 a = s_in[(2 * pr) * PIN + 2 * pc];
            float2 b = s_in[(2 * pr) * PIN + 2 * pc + 1];
            float2 c2 = s_in[(2 * pr + 1) * PIN + 2 * pc];
            float2 d = s_in[(2 * pr + 1) * PIN + 2 * pc + 1];
            float xp = 0.25f * (a.x + b.x + c2.x + d.x);
            float yp = 0.25f * (a.y + b.y + c2.y + d.y);
            int Ho = H >> 1, Wo = W >> 1;
            size_t o = (size_t)img * Ho * Wo + (size_t)((row0 >> 1) + pr) * Wo + (col0 >> 1) + pc;
            XP[o] = xp;
            YP[o] = yp;
        }
    }

    // ---- horizontal pass: 4-column units, packed moments ----
    for (int u = tid; u < TIH * CG; u += NT) {
        int r = u / CG, cg = (u % CG) * 4;
        const float2* prow = &s_in[r * PIN + cg];
        u64 m01[4] = {0, 0, 0, 0};
        u64 m23[4] = {0, 0, 0, 0};
        float mzz[4] = {0.f, 0.f, 0.f, 0.f};
        #pragma unroll
        for (int i = 0; i < 14; i++) {
            float2 v = prow[i];
            u64 vp = pk2(v.x, v.y);
            u64 q  = mul2(vp, vp);
            float z = v.x + v.y;
            float z2 = z * z;
            #pragma unroll
            for (int j = 0; j < 4; j++) {
                if (i - j >= 0 && i - j < WS) {
                    m01[j] = fma2(wpk[i - j], vp, m01[j]);
                    m23[j] = fma2(wpk[i - j], q,  m23[j]);
                    mzz[j] = fmaf(wreg[i - j], z2, mzz[j]);
                }
            }
        }
        int o = r * PH + cg;
        #pragma unroll
        for (int j = 0; j < 4; j++) {
            float a, b;
            up2(m01[j], a, b); h01[o + j] = make_float2(a, b);
            up2(m23[j], a, b); h23[o + j] = make_float2(a, b);
            hzz[o + j] = mzz[j];
        }
    }
    __syncthreads();

    // ---- vertical pass + SSIM math ----
    const float C1 = 0.01f * 0.01f;
    const float C2 = 0.03f * 0.03f;
    const int c  = tid % TW;
    const int r0 = (tid / TW) * RPT;
    const int Hout = H - 10, Wout = W - 10;
    const bool colok = (col0 + c) < Wout;

    u64 a01[RPT], a23[RPT];
    float az[RPT];
    #pragma unroll
    for (int j = 0; j < RPT; j++) { a01[j] = 0; a23[j] = 0; az[j] = 0.f; }

    #pragma unroll
    for (int k = 0; k < RPT + 10; k++) {
        float2 v01 = h01[(r0 + k) * PH + c];
        float2 v23 = h23[(r0 + k) * PH + c];
        float  vz  = hzz[(r0 + k) * PH + c];
        u64 p01 = pk2(v01.x, v01.y);
        u64 p23 = pk2(v23.x, v23.y);
        #pragma unroll
        for (int j = 0; j < RPT; j++) {
            int t = k - j;
            if (t >= 0 && t < WS) {
                a01[j] = fma2(wpk[t], p01, a01[j]);
                a23[j] = fma2(wpk[t], p23, a23[j]);
                az[j]  = fmaf(wreg[t], vz, az[j]);
            }
        }
    }

    float cs_sum = 0.f, ss_sum = 0.f;
    #pragma unroll
    for (int j = 0; j < RPT; j++) {
        if (colok && (row0 + r0 + j) < Hout) {
            float mu1, mu2, e11, e22;
            up2(a01[j], mu1, mu2);
            up2(a23[j], e11, e22);
            float e12 = 0.5f * (az[j] - e11 - e22);
            float s1  = e11 - mu1 * mu1;
            float s2  = e22 - mu2 * mu2;
            float s12 = e12 - mu1 * mu2;
            float num = 2.f * s12 + C2;
            float den = s1 + s2 + C2;
            float cs  = num / den;
            float lum = (2.f * mu1 * mu2 + C1) / (mu1 * mu1 + mu2 * mu2 + C1);
            cs_sum += cs;
            ss_sum += lum * cs;
        }
    }

    // warp + block reduction
    #pragma unroll
    for (int o = 16; o > 0; o >>= 1) {
        cs_sum += __shfl_down_sync(0xffffffffu, cs_sum, o);
        ss_sum += __shfl_down_sync(0xffffffffu, ss_sum, o);
    }
    if ((tid & 31) == 0) { red0[tid >> 5] = cs_sum; red1[tid >> 5] = ss_sum; }
    __syncthreads();
    if (tid == 0) {
        double a = 0.0, b = 0.0;
        #pragma unroll
        for (int w = 0; w < NW; w++) { a += red0[w]; b += red1[w]; }
        atomicAdd(&g_cs[level], a);
        atomicAdd(&g_ss[level], b);
    }
}

// ---------------- final combine ----------------------------------------------
__global__ void finish_kernel(float* __restrict__ out)
{
    if (threadIdx.x != 0) return;
    const double w[5] = {0.0448, 0.2856, 0.3001, 0.2363, 0.1333};
    double ms = 1.0;
    #pragma unroll
    for (int l = 0; l < 5; l++) {
        int Hl = 512 >> l;
        double n  = 48.0 * (double)(Hl - 10) * (double)(Hl - 10);
        double cs = g_cs[l] / n; if (cs < 0.0) cs = 0.0; cs = (cs + 1.0) * 0.5;
        double ss = g_ss[l] / n; if (ss < 0.0) ss = 0.0; ss = (ss + 1.0) * 0.5;
        double v  = (l < 4) ? cs : ss;
        ms *= pow(v, w[l]);
    }
    out[0] = (float)(1.0 - ms);
}

// ---------------- host launch -------------------------------------------------
static inline dim3 conv_grid(int H, int W, int tw, int th) {
    int Hout = H - 10, Wout = W - 10;
    return dim3((Wout + tw - 1) / tw, (Hout + th - 1) / th, BC);
}

extern "C" void kernel_launch(void* const* d_in, const int* in_sizes, int n_in,
                              void* d_out, int out_size)
{
    const float* X0 = (const float*)d_in[0];
    const float* Y0 = (const float*)d_in[1];
    float* out = (float*)d_out;

    float *xa, *ya, *xb, *yb;
    cudaGetSymbolAddress((void**)&xa, g_xa);
    cudaGetSymbolAddress((void**)&ya, g_ya);
    cudaGetSymbolAddress((void**)&xb, g_xb);
    cudaGetSymbolAddress((void**)&yb, g_yb);

    init_kernel<<<1, 32>>>();

    // level 0: 512 -> pool into xa/ya (256)
    ssim_kernel<32, 32, 256><<<conv_grid(512, 512, 32, 32), 256>>>(X0, Y0, xa, ya, 512, 512, 0, 1);
    // level 1: 256 -> pool into xb/yb (128)
    ssim_kernel<32, 32, 256><<<conv_grid(256, 256, 32, 32), 256>>>(xa, ya, xb, yb, 256, 256, 1, 1);
    // level 2: 128 -> pool into xa/ya (64)  (small tiles for latency)
    ssim_kernel<16, 16, 128><<<conv_grid(128, 128, 16, 16), 128>>>(xb, yb, xa, ya, 128, 128, 2, 1);
    // level 3: 64 -> pool into xb/yb (32)
    ssim_kernel<16, 16, 128><<<conv_grid(64, 64, 16, 16), 128>>>(xa, ya, xb, yb, 64, 64, 3, 1);
    // level 4: 32, no pool
    ssim_kernel<16, 16, 128><<<conv_grid(32, 32, 16, 16), 128>>>(xb, yb, nullptr, nullptr, 32, 32, 4, 0);

    finish_kernel<<<1, 32>>>(out);
}